// round 5
// baseline (speedup 1.0000x reference)
#include <cuda_runtime.h>

// x_seq (T=16, N=8, C=64, H=64, W=64) fp32; conv_weight (64,64,3,3) fp32.
// z = conv3x3(pad=1) over B=T*N=128 images, then LIF scan over T.
#define T_  16
#define NB  8
#define C_  64
#define H_  64
#define W_  64
#define B_  (T_ * NB)
#define HW_ (H_ * W_)
#define CHW (C_ * HW_)
#define INNER (NB * CHW)        // 2097152 per timestep

#define TS_H 16
#define TS_W 32                 // 2 pixels per thread (w-adjacent pair)
#define CIN_CHUNK 16
#define COUT_PER  8             // 8 cout groups
#define XROW 34                 // halo row: 32 + 2
#define XCI  (18 * XROW)        // 612 floats per ci slice

// Conv output scratch (static device global — no allocation).
__device__ float g_z[(size_t)B_ * CHW];

typedef unsigned long long u64;

__device__ __forceinline__ void fma2(u64& acc, u64 x2, u64 w2) {
    asm("fma.rn.f32x2 %0, %1, %2, %3;" : "=l"(acc) : "l"(x2), "l"(w2), "l"(acc));
}
__device__ __forceinline__ u64 pack2(float lo, float hi) {
    u64 r; asm("mov.b64 %0, {%1, %2};" : "=l"(r) : "f"(lo), "f"(hi)); return r;
}
__device__ __forceinline__ void unpack2(u64 v, float& lo, float& hi) {
    asm("mov.b64 {%0, %1}, %2;" : "=f"(lo), "=f"(hi) : "l"(v));
}

// ---------------------------------------------------------------------------
// Direct 3x3 conv, packed-pixel FFMA2. One block = 1 image x 32x16 tile x
// 8 couts. Weights staged duplicated-pair [(w,w)] in smem so inner weight
// reads are warp-uniform LDS.128 delivering 2 packed operands.
// Precision: fp32 chain per 4-cin chunk, chunk folded into double (exact).
// Accumulation ORDER identical to the R3 passing kernel.
// ---------------------------------------------------------------------------
__global__ __launch_bounds__(256, 2)
void conv3x3_kernel(const float* __restrict__ x, const float* __restrict__ w) {
    __shared__ float  xs[CIN_CHUNK * XCI];                 // 39168 B
    __shared__ float2 ws[CIN_CHUNK * 9 * COUT_PER];        //  9216 B

    const int tile = blockIdx.x;          // 0..7 : 2 across x 4 down
    const int b    = blockIdx.y;          // 0..127
    const int cg   = blockIdx.z;          // 0..7 cout group
    const int h0 = (tile >> 1) * TS_H;
    const int w0 = (tile & 1) * TS_W;
    const int tid = threadIdx.x;
    const int p  = tid & 15;              // pixel-pair col: covers w0+2p, w0+2p+1
    const int py = tid >> 4;              // row 0..15

    double accd0[COUT_PER], accd1[COUT_PER];
#pragma unroll
    for (int i = 0; i < COUT_PER; i++) { accd0[i] = 0.0; accd1[i] = 0.0; }

    for (int cc = 0; cc < C_; cc += CIN_CHUNK) {
        // ---- stage input tile with halo (zero padded) ----
        for (int idx = tid; idx < CIN_CHUNK * XCI; idx += 256) {
            int ci  = idx / XCI;
            int rem = idx - ci * XCI;
            int r = rem / XROW, c = rem - r * XROW;
            int gh = h0 + r - 1, gw = w0 + c - 1;
            float v = 0.0f;
            if ((unsigned)gh < (unsigned)H_ && (unsigned)gw < (unsigned)W_)
                v = x[(size_t)b * CHW + (size_t)(cc + ci) * HW_ + gh * W_ + gw];
            xs[idx] = v;
        }
        // ---- stage weights as duplicated pairs ws[(ci*9+k)*8+co] = (w,w) ----
        for (int idx = tid; idx < CIN_CHUNK * 9 * COUT_PER; idx += 256) {
            int ci  = idx / (9 * COUT_PER);
            int rem = idx - ci * (9 * COUT_PER);
            int k  = rem >> 3;
            int co = rem & 7;
            float v = w[((size_t)(cg * COUT_PER + co) * C_ + (cc + ci)) * 9 + k];
            ws[idx] = make_float2(v, v);
        }
        __syncthreads();

#pragma unroll 1
        for (int c4 = 0; c4 < CIN_CHUNK / 4; c4++) {
            u64 accf[COUT_PER];
#pragma unroll
            for (int i = 0; i < COUT_PER; i++) accf[i] = 0ULL;

#pragma unroll
            for (int ci4 = 0; ci4 < 4; ci4++) {
                const int ci = c4 * 4 + ci4;
                const float* xb = &xs[ci * XCI + py * XROW + 2 * p];
                u64 xp[9];
#pragma unroll
                for (int kh = 0; kh < 3; kh++) {
                    // two aligned 8B loads cover the 4 needed columns
                    u64 d0 = *(const u64*)&xb[kh * XROW];
                    u64 d1 = *(const u64*)&xb[kh * XROW + 2];
                    float a0, a1, a2, a3;
                    unpack2(d0, a0, a1);
                    unpack2(d1, a2, a3);
                    xp[kh * 3 + 0] = d0;
                    xp[kh * 3 + 1] = pack2(a1, a2);
                    xp[kh * 3 + 2] = d1;
                    (void)a0; (void)a3;
                }
#pragma unroll
                for (int k = 0; k < 9; k++) {
                    const ulonglong2* wq =
                        (const ulonglong2*)&ws[(ci * 9 + k) * COUT_PER];
#pragma unroll
                    for (int q = 0; q < COUT_PER / 2; q++) {
                        ulonglong2 wv = wq[q];
                        fma2(accf[q * 2 + 0], xp[k], wv.x);
                        fma2(accf[q * 2 + 1], xp[k], wv.y);
                    }
                }
            }
            // exact fold of the 4-cin chunk into double totals
#pragma unroll
            for (int i = 0; i < COUT_PER; i++) {
                float lo, hi;
                unpack2(accf[i], lo, hi);
                accd0[i] += (double)lo;
                accd1[i] += (double)hi;
            }
        }
        __syncthreads();
    }

    const int h = h0 + py, wcol = w0 + 2 * p;
#pragma unroll
    for (int co = 0; co < COUT_PER; co++) {
        float2 r = make_float2((float)accd0[co], (float)accd1[co]);
        *(float2*)&g_z[(size_t)b * CHW +
                       (size_t)(cg * COUT_PER + co) * HW_ + h * W_ + wcol] = r;
    }
}

// ---------------------------------------------------------------------------
// LIF scan over T, float4-vectorized: v += (x - v)/2 ; spike=(v>=1); reset 0.
// ---------------------------------------------------------------------------
__global__ __launch_bounds__(256)
void lif_kernel(float* __restrict__ out) {
    int i = blockIdx.x * blockDim.x + threadIdx.x;   // float4 index
    const float4* z4 = (const float4*)g_z;
    float4* o4 = (float4*)out;
    float4 v = make_float4(0.f, 0.f, 0.f, 0.f);
#pragma unroll
    for (int t = 0; t < T_; t++) {
        float4 xv = z4[(size_t)t * (INNER / 4) + i];
        v.x = v.x + (xv.x - v.x) * 0.5f;
        v.y = v.y + (xv.y - v.y) * 0.5f;
        v.z = v.z + (xv.z - v.z) * 0.5f;
        v.w = v.w + (xv.w - v.w) * 0.5f;
        float4 s;
        s.x = (v.x >= 1.0f) ? 1.0f : 0.0f;
        s.y = (v.y >= 1.0f) ? 1.0f : 0.0f;
        s.z = (v.z >= 1.0f) ? 1.0f : 0.0f;
        s.w = (v.w >= 1.0f) ? 1.0f : 0.0f;
        o4[(size_t)t * (INNER / 4) + i] = s;
        if (v.x >= 1.0f) v.x = 0.0f;
        if (v.y >= 1.0f) v.y = 0.0f;
        if (v.z >= 1.0f) v.z = 0.0f;
        if (v.w >= 1.0f) v.w = 0.0f;
    }
}

extern "C" void kernel_launch(void* const* d_in, const int* in_sizes, int n_in,
                              void* d_out, int out_size) {
    const float* x = (const float*)d_in[0];
    const float* w = (const float*)d_in[1];
    float* out = (float*)d_out;

    dim3 grid(8, B_, 8);    // 2x4 tiles, 128 images, 8 cout groups
    conv3x3_kernel<<<grid, 256>>>(x, w);
    lif_kernel<<<(INNER / 4) / 256, 256>>>(out);
}

// round 7
// speedup vs baseline: 1.7268x; 1.7268x over previous
#include <cuda_runtime.h>

// x_seq (T=16, N=8, C=64, H=64, W=64) fp32; conv_weight (64,64,3,3) fp32.
// z = conv3x3(pad=1) over B=T*N=128 images, then LIF scan over T.
#define T_  16
#define NB  8
#define C_  64
#define H_  64
#define W_  64
#define B_  (T_ * NB)
#define HW_ (H_ * W_)
#define CHW (C_ * HW_)
#define INNER (NB * CHW)        // 2097152 per timestep

#define TS_H 16
#define TS_W 32                 // tile 32 wide; 2 adjacent pixels per thread
#define CIN_CHUNK 8
#define COUT_PER  16            // 4 cout groups
#define XROW 35                 // 32 + 2 halo, padded to odd for bank-free strided loads
#define XCI  (18 * XROW)        // 630 floats per ci slice

// Conv output scratch (static device global — no allocation).
__device__ float g_z[(size_t)B_ * CHW];

// ---------------------------------------------------------------------------
// Direct 3x3 conv. One block = 1 image x 32x16 tile x 16 couts; each thread
// computes 2 horizontally-adjacent pixels (shared weights, overlapping taps).
// Weights staged transposed [ci][tap][cout] => inner reads are warp-uniform
// broadcast LDS.128. Precision: fp32 FFMA over 4-ci chunks, chunks folded
// into an fp32 running total (two-level summation, ~7 ulp).
// ---------------------------------------------------------------------------
__global__ __launch_bounds__(256, 2)
void conv3x3_kernel(const float* __restrict__ x, const float* __restrict__ w) {
    __shared__ float xs[CIN_CHUNK * XCI];                // 20160 B
    __shared__ float ws[CIN_CHUNK * 9 * COUT_PER];       //  4608 B

    const int tile = blockIdx.x;          // 0..7 : 2 across x 4 down
    const int b    = blockIdx.y;          // 0..127
    const int cg   = blockIdx.z;          // 0..3 cout group
    const int h0 = (tile >> 1) * TS_H;
    const int w0 = (tile & 1) * TS_W;
    const int tid = threadIdx.x;
    const int p  = tid & 15;              // pixel pair covers columns 2p, 2p+1
    const int py = tid >> 4;              // row 0..15

    float tot0[COUT_PER], tot1[COUT_PER];
#pragma unroll
    for (int i = 0; i < COUT_PER; i++) { tot0[i] = 0.0f; tot1[i] = 0.0f; }

    for (int cc = 0; cc < C_; cc += CIN_CHUNK) {
        // ---- stage input tile with halo (zero padded) ----
        for (int idx = tid; idx < CIN_CHUNK * XCI; idx += 256) {
            int ci  = idx / XCI;
            int rem = idx - ci * XCI;
            int r = rem / XROW, c = rem - r * XROW;
            float v = 0.0f;
            if (c < 34) {
                int gh = h0 + r - 1, gw = w0 + c - 1;
                if ((unsigned)gh < (unsigned)H_ && (unsigned)gw < (unsigned)W_)
                    v = x[(size_t)b * CHW + (size_t)(cc + ci) * HW_ + gh * W_ + gw];
            }
            xs[idx] = v;
        }
        // ---- stage weights transposed: ws[(ci*9 + k)*16 + co] ----
        for (int idx = tid; idx < CIN_CHUNK * 9 * COUT_PER; idx += 256) {
            int ci  = idx / (9 * COUT_PER);
            int rem = idx - ci * (9 * COUT_PER);
            int k  = rem >> 4;
            int co = rem & 15;
            ws[idx] = w[((size_t)(cg * COUT_PER + co) * C_ + (cc + ci)) * 9 + k];
        }
        __syncthreads();

#pragma unroll 1
        for (int c4 = 0; c4 < CIN_CHUNK / 4; c4++) {
            float a0[COUT_PER], a1[COUT_PER];
#pragma unroll
            for (int i = 0; i < COUT_PER; i++) { a0[i] = 0.0f; a1[i] = 0.0f; }

#pragma unroll
            for (int ci4 = 0; ci4 < 4; ci4++) {
                const int ci = c4 * 4 + ci4;
                const float* xb = &xs[ci * XCI + py * XROW + 2 * p];
                float xw[3][4];
#pragma unroll
                for (int kh = 0; kh < 3; kh++)
#pragma unroll
                    for (int c = 0; c < 4; c++)
                        xw[kh][c] = xb[kh * XROW + c];

#pragma unroll
                for (int kh = 0; kh < 3; kh++) {
#pragma unroll
                    for (int kw = 0; kw < 3; kw++) {
                        const float xv0 = xw[kh][kw];
                        const float xv1 = xw[kh][kw + 1];
                        const float4* wp =
                            (const float4*)&ws[((ci * 3 + kh) * 3 + kw) * COUT_PER];
#pragma unroll
                        for (int q = 0; q < COUT_PER / 4; q++) {
                            float4 wv = wp[q];
                            a0[q*4+0] = __fmaf_rn(xv0, wv.x, a0[q*4+0]);
                            a1[q*4+0] = __fmaf_rn(xv1, wv.x, a1[q*4+0]);
                            a0[q*4+1] = __fmaf_rn(xv0, wv.y, a0[q*4+1]);
                            a1[q*4+1] = __fmaf_rn(xv1, wv.y, a1[q*4+1]);
                            a0[q*4+2] = __fmaf_rn(xv0, wv.z, a0[q*4+2]);
                            a1[q*4+2] = __fmaf_rn(xv1, wv.z, a1[q*4+2]);
                            a0[q*4+3] = __fmaf_rn(xv0, wv.w, a0[q*4+3]);
                            a1[q*4+3] = __fmaf_rn(xv1, wv.w, a1[q*4+3]);
                        }
                    }
                }
            }
            // fold 4-ci chunk into fp32 running totals (two-level summation)
#pragma unroll
            for (int i = 0; i < COUT_PER; i++) {
                tot0[i] += a0[i];
                tot1[i] += a1[i];
            }
        }
        __syncthreads();
    }

    const int h = h0 + py, wcol = w0 + 2 * p;
#pragma unroll
    for (int co = 0; co < COUT_PER; co++) {
        float2 r = make_float2(tot0[co], tot1[co]);
        *(float2*)&g_z[(size_t)b * CHW +
                       (size_t)(cg * COUT_PER + co) * HW_ + h * W_ + wcol] = r;
    }
}

// ---------------------------------------------------------------------------
// LIF scan over T, float4-vectorized: v += (x - v)/2 ; spike=(v>=1); reset 0.
// ---------------------------------------------------------------------------
__global__ __launch_bounds__(256)
void lif_kernel(float* __restrict__ out) {
    int i = blockIdx.x * blockDim.x + threadIdx.x;   // float4 index
    const float4* z4 = (const float4*)g_z;
    float4* o4 = (float4*)out;
    float4 v = make_float4(0.f, 0.f, 0.f, 0.f);
#pragma unroll
    for (int t = 0; t < T_; t++) {
        float4 xv = z4[(size_t)t * (INNER / 4) + i];
        v.x = v.x + (xv.x - v.x) * 0.5f;
        v.y = v.y + (xv.y - v.y) * 0.5f;
        v.z = v.z + (xv.z - v.z) * 0.5f;
        v.w = v.w + (xv.w - v.w) * 0.5f;
        float4 s;
        s.x = (v.x >= 1.0f) ? 1.0f : 0.0f;
        s.y = (v.y >= 1.0f) ? 1.0f : 0.0f;
        s.z = (v.z >= 1.0f) ? 1.0f : 0.0f;
        s.w = (v.w >= 1.0f) ? 1.0f : 0.0f;
        o4[(size_t)t * (INNER / 4) + i] = s;
        if (v.x >= 1.0f) v.x = 0.0f;
        if (v.y >= 1.0f) v.y = 0.0f;
        if (v.z >= 1.0f) v.z = 0.0f;
        if (v.w >= 1.0f) v.w = 0.0f;
    }
}

extern "C" void kernel_launch(void* const* d_in, const int* in_sizes, int n_in,
                              void* d_out, int out_size) {
    const float* x = (const float*)d_in[0];
    const float* w = (const float*)d_in[1];
    float* out = (float*)d_out;

    dim3 grid(8, B_, 4);    // 2x4 tiles, 128 images, 4 cout groups
    conv3x3_kernel<<<grid, 256>>>(x, w);
    lif_kernel<<<(INNER / 4) / 256, 256>>>(out);
}

// round 8
// speedup vs baseline: 3.1004x; 1.7955x over previous
#include <cuda_runtime.h>

// x_seq (T=16, N=8, C=64, H=64, W=64) fp32; conv_weight (64,64,3,3) fp32.
// z = conv3x3(pad=1) over B=T*N=128 images, then LIF scan over T.
#define T_  16
#define NB  8
#define C_  64
#define H_  64
#define W_  64
#define B_  (T_ * NB)
#define HW_ (H_ * W_)
#define CHW (C_ * HW_)
#define INNER (NB * CHW)        // 2097152 per timestep

#define TS_H 16
#define TS_W 32                 // tile 32 wide; 2 adjacent pixels per thread
#define CIN_CHUNK 4             // per double-buffer stage
#define NCHUNK (C_ / CIN_CHUNK) // 16
#define COUT_PER  16            // 4 cout groups
#define XROW 35                 // 32 + 2 halo, padded odd (bank-free strided loads)
#define XCI  (18 * XROW)        // 630 floats per ci slice
#define XELEMS (CIN_CHUNK * XCI)        // 2520 per buffer
#define WELEMS (CIN_CHUNK * 9 * COUT_PER) // 576 per buffer
#define XSLOTS 10               // ceil(2520/256)

// Conv output scratch (static device global — no allocation).
__device__ float g_z[(size_t)B_ * CHW];

__device__ __forceinline__ void cpa4(unsigned saddr, const float* g) {
    asm volatile("cp.async.ca.shared.global [%0], [%1], 4;"
                 :: "r"(saddr), "l"(g) : "memory");
}
#define CP_COMMIT() asm volatile("cp.async.commit_group;" ::: "memory")
#define CP_WAIT1()  asm volatile("cp.async.wait_group 1;" ::: "memory")
#define CP_WAIT0()  asm volatile("cp.async.wait_group 0;" ::: "memory")

// ---------------------------------------------------------------------------
// Direct 3x3 conv, cp.async double-buffered over cin chunks of 4.
// One block = 1 image x 32x16 tile x 16 couts; each thread computes 2
// horizontally-adjacent pixels. Weights staged transposed [ci][tap][cout]
// => inner weight reads are warp-uniform broadcast LDS.128.
// Precision: fp32 FFMA per 4-ci chunk, chunks folded in order into fp32
// running totals (identical accumulation order to the R6 passing kernel).
// ---------------------------------------------------------------------------
__global__ __launch_bounds__(256, 2)
void conv3x3_kernel(const float* __restrict__ x, const float* __restrict__ w) {
    __shared__ float xs[2][XELEMS];      // 2 x 10080 B
    __shared__ float ws[2][WELEMS];      // 2 x  2304 B

    const int tile = blockIdx.x;          // 0..7 : 2 across x 4 down
    const int b    = blockIdx.y;          // 0..127
    const int cg   = blockIdx.z;          // 0..3 cout group
    const int h0 = (tile >> 1) * TS_H;
    const int w0 = (tile & 1) * TS_W;
    const int tid = threadIdx.x;
    const int p  = tid & 15;              // pixel pair covers columns 2p, 2p+1
    const int py = tid >> 4;              // row 0..15

    // ---- precompute staging slots (fixed per thread for all chunks) ----
    int xrel[XSLOTS];
    unsigned vmask = 0;
    {
#pragma unroll
        for (int s = 0; s < XSLOTS; s++) {
            int idx = tid + 256 * s;
            int ci  = idx / XCI;
            int rem = idx - ci * XCI;
            int r = rem / XROW, c = rem - r * XROW;
            int gh = h0 + r - 1, gw = w0 + c - 1;
            bool valid = (idx < XELEMS) && (c < 34) &&
                         ((unsigned)gh < (unsigned)H_) &&
                         ((unsigned)gw < (unsigned)W_);
            xrel[s] = ci * HW_ + gh * W_ + gw;
            if (valid) vmask |= (1u << s);
        }
    }
    int wrel[3];
#pragma unroll
    for (int s = 0; s < 3; s++) {
        int idx = (tid + 256 * s) % WELEMS;
        int ci  = idx / (9 * COUT_PER);
        int rem = idx - ci * (9 * COUT_PER);
        int k  = rem >> 4;
        int co = rem & 15;
        wrel[s] = (cg * COUT_PER + co) * (C_ * 9) + ci * 9 + k;
    }
    const bool w2v = (tid < WELEMS - 512);

    const unsigned xs0 = (unsigned)__cvta_generic_to_shared(&xs[0][0]);
    const unsigned xs1 = (unsigned)__cvta_generic_to_shared(&xs[1][0]);
    const unsigned ws0 = (unsigned)__cvta_generic_to_shared(&ws[0][0]);
    const unsigned ws1 = (unsigned)__cvta_generic_to_shared(&ws[1][0]);
    const float* xbase = x + (size_t)b * CHW;

    // ---- zero both xs buffers once (halo slots are never rewritten) ----
    for (int i = tid; i < 2 * XELEMS; i += 256) (&xs[0][0])[i] = 0.0f;
    __syncthreads();

    // ---- prefetch chunk 0 ----
    {
        const float* xp = xbase;
        const float* wp = w;
#pragma unroll
        for (int s = 0; s < XSLOTS; s++)
            if (vmask & (1u << s))
                cpa4(xs0 + (unsigned)(tid + 256 * s) * 4u, xp + xrel[s]);
        cpa4(ws0 + (unsigned)tid * 4u, wp + wrel[0]);
        cpa4(ws0 + (unsigned)(tid + 256) * 4u, wp + wrel[1]);
        if (w2v) cpa4(ws0 + (unsigned)(tid + 512) * 4u, wp + wrel[2]);
        CP_COMMIT();
    }

    float tot0[COUT_PER], tot1[COUT_PER];
#pragma unroll
    for (int i = 0; i < COUT_PER; i++) { tot0[i] = 0.0f; tot1[i] = 0.0f; }

#pragma unroll 1
    for (int ch = 0; ch < NCHUNK; ch++) {
        const int bsel = ch & 1;
        // prefetch next chunk into the other buffer
        if (ch + 1 < NCHUNK) {
            const float* xp = xbase + (ch + 1) * CIN_CHUNK * HW_;
            const float* wp = w + (ch + 1) * CIN_CHUNK * 9;
            const unsigned xb = bsel ? xs0 : xs1;
            const unsigned wb = bsel ? ws0 : ws1;
#pragma unroll
            for (int s = 0; s < XSLOTS; s++)
                if (vmask & (1u << s))
                    cpa4(xb + (unsigned)(tid + 256 * s) * 4u, xp + xrel[s]);
            cpa4(wb + (unsigned)tid * 4u, wp + wrel[0]);
            cpa4(wb + (unsigned)(tid + 256) * 4u, wp + wrel[1]);
            if (w2v) cpa4(wb + (unsigned)(tid + 512) * 4u, wp + wrel[2]);
            CP_COMMIT();
            CP_WAIT1();        // current chunk's group done; next stays in flight
        } else {
            CP_WAIT0();
        }
        __syncthreads();

        // ---- compute on current buffer: 4 ci, fold into totals ----
        float a0[COUT_PER], a1[COUT_PER];
#pragma unroll
        for (int i = 0; i < COUT_PER; i++) { a0[i] = 0.0f; a1[i] = 0.0f; }

#pragma unroll
        for (int ci = 0; ci < CIN_CHUNK; ci++) {
            const float* xb = &xs[bsel][ci * XCI + py * XROW + 2 * p];
            float xw[3][4];
#pragma unroll
            for (int kh = 0; kh < 3; kh++)
#pragma unroll
                for (int c = 0; c < 4; c++)
                    xw[kh][c] = xb[kh * XROW + c];

#pragma unroll
            for (int kh = 0; kh < 3; kh++) {
#pragma unroll
                for (int kw = 0; kw < 3; kw++) {
                    const float xv0 = xw[kh][kw];
                    const float xv1 = xw[kh][kw + 1];
                    const float4* wp4 =
                        (const float4*)&ws[bsel][((ci * 3 + kh) * 3 + kw) * COUT_PER];
#pragma unroll
                    for (int q = 0; q < COUT_PER / 4; q++) {
                        float4 wv = wp4[q];
                        a0[q*4+0] = __fmaf_rn(xv0, wv.x, a0[q*4+0]);
                        a1[q*4+0] = __fmaf_rn(xv1, wv.x, a1[q*4+0]);
                        a0[q*4+1] = __fmaf_rn(xv0, wv.y, a0[q*4+1]);
                        a1[q*4+1] = __fmaf_rn(xv1, wv.y, a1[q*4+1]);
                        a0[q*4+2] = __fmaf_rn(xv0, wv.z, a0[q*4+2]);
                        a1[q*4+2] = __fmaf_rn(xv1, wv.z, a1[q*4+2]);
                        a0[q*4+3] = __fmaf_rn(xv0, wv.w, a0[q*4+3]);
                        a1[q*4+3] = __fmaf_rn(xv1, wv.w, a1[q*4+3]);
                    }
                }
            }
        }
#pragma unroll
        for (int i = 0; i < COUT_PER; i++) {
            tot0[i] += a0[i];
            tot1[i] += a1[i];
        }
        __syncthreads();   // buffer bsel safe to overwrite at chunk ch+2
    }

    const int h = h0 + py, wcol = w0 + 2 * p;
#pragma unroll
    for (int co = 0; co < COUT_PER; co++) {
        float2 r = make_float2(tot0[co], tot1[co]);
        *(float2*)&g_z[(size_t)b * CHW +
                       (size_t)(cg * COUT_PER + co) * HW_ + h * W_ + wcol] = r;
    }
}

// ---------------------------------------------------------------------------
// LIF scan over T, float4-vectorized: v += (x - v)/2 ; spike=(v>=1); reset 0.
// ---------------------------------------------------------------------------
__global__ __launch_bounds__(256)
void lif_kernel(float* __restrict__ out) {
    int i = blockIdx.x * blockDim.x + threadIdx.x;   // float4 index
    const float4* z4 = (const float4*)g_z;
    float4* o4 = (float4*)out;
    float4 v = make_float4(0.f, 0.f, 0.f, 0.f);
#pragma unroll
    for (int t = 0; t < T_; t++) {
        float4 xv = z4[(size_t)t * (INNER / 4) + i];
        v.x = v.x + (xv.x - v.x) * 0.5f;
        v.y = v.y + (xv.y - v.y) * 0.5f;
        v.z = v.z + (xv.z - v.z) * 0.5f;
        v.w = v.w + (xv.w - v.w) * 0.5f;
        float4 s;
        s.x = (v.x >= 1.0f) ? 1.0f : 0.0f;
        s.y = (v.y >= 1.0f) ? 1.0f : 0.0f;
        s.z = (v.z >= 1.0f) ? 1.0f : 0.0f;
        s.w = (v.w >= 1.0f) ? 1.0f : 0.0f;
        o4[(size_t)t * (INNER / 4) + i] = s;
        if (v.x >= 1.0f) v.x = 0.0f;
        if (v.y >= 1.0f) v.y = 0.0f;
        if (v.z >= 1.0f) v.z = 0.0f;
        if (v.w >= 1.0f) v.w = 0.0f;
    }
}

extern "C" void kernel_launch(void* const* d_in, const int* in_sizes, int n_in,
                              void* d_out, int out_size) {
    const float* x = (const float*)d_in[0];
    const float* w = (const float*)d_in[1];
    float* out = (float*)d_out;

    dim3 grid(8, B_, 4);    // 2x4 tiles, 128 images, 4 cout groups
    conv3x3_kernel<<<grid, 256>>>(x, w);
    lif_kernel<<<(INNER / 4) / 256, 256>>>(out);
}

// round 9
// speedup vs baseline: 3.4452x; 1.1112x over previous
#include <cuda_runtime.h>

// x_seq (T=16, N=8, C=64, H=64, W=64) fp32; conv_weight (64,64,3,3) fp32.
// z = conv3x3(pad=1) over B=T*N=128 images, then LIF scan over T.
#define T_  16
#define NB  8
#define C_  64
#define H_  64
#define W_  64
#define B_  (T_ * NB)
#define HW_ (H_ * W_)
#define CHW (C_ * HW_)
#define INNER (NB * CHW)        // 2097152 per timestep

#define TS_H 16
#define TS_W 32                 // tile 32 wide; 2 adjacent pixels per thread
#define CIN_CHUNK 4             // per double-buffer stage
#define NCHUNK (C_ / CIN_CHUNK) // 16
#define COUT_PER  16            // 4 cout groups
#define XROW 35                 // 32 + 2 halo, padded odd (bank-free strided loads)
#define XCI  (18 * XROW)        // 630 floats per ci slice
#define XELEMS (CIN_CHUNK * XCI)          // 2520 per buffer
#define WELEMS (CIN_CHUNK * 9 * COUT_PER) // 576 per buffer
#define XSLOTS 10               // ceil(2520/256)

// Conv output scratch (static device global — no allocation).
__device__ float g_z[(size_t)B_ * CHW];

typedef unsigned long long u64;

// Packed fp32x2 ops (lane-wise rn-rounded fp32 — bit-identical per lane to
// scalar __fmaf_rn / fadd.rn, so accumulation order matches the scalar kernel).
__device__ __forceinline__ void fma2(u64& a, u64 x, u64 w) {
    asm("fma.rn.f32x2 %0, %1, %2, %3;" : "=l"(a) : "l"(x), "l"(w), "l"(a));
}
__device__ __forceinline__ void add2(u64& a, u64 b) {
    asm("add.rn.f32x2 %0, %1, %2;" : "=l"(a) : "l"(a), "l"(b));
}
__device__ __forceinline__ u64 dup2(float v) {
    u64 r; asm("mov.b64 %0, {%1, %1};" : "=l"(r) : "f"(v)); return r;
}
__device__ __forceinline__ void unpk(u64 v, float& lo, float& hi) {
    asm("mov.b64 {%0, %1}, %2;" : "=f"(lo), "=f"(hi) : "l"(v));
}

__device__ __forceinline__ void cpa4(unsigned saddr, const float* g) {
    asm volatile("cp.async.ca.shared.global [%0], [%1], 4;"
                 :: "r"(saddr), "l"(g) : "memory");
}
#define CP_COMMIT() asm volatile("cp.async.commit_group;" ::: "memory")
#define CP_WAIT1()  asm volatile("cp.async.wait_group 1;" ::: "memory")
#define CP_WAIT0()  asm volatile("cp.async.wait_group 0;" ::: "memory")

// ---------------------------------------------------------------------------
// Direct 3x3 conv, cp.async double-buffered, packed-cout FFMA2.
// One block = 1 image x 32x16 tile x 16 couts; each thread computes 2
// horizontally-adjacent pixels. Accumulator lanes pack (co, co+1): weight
// operand pairs come straight out of smem as u64 halves of broadcast
// LDS.128 (no duplication); input taps are splatted (x,x) once per column.
// Per ci: 144 FFMA2 + ~72 other => FFMA2-pipe-bound.
// ---------------------------------------------------------------------------
__global__ __launch_bounds__(256, 2)
void conv3x3_kernel(const float* __restrict__ x, const float* __restrict__ w) {
    __shared__ __align__(16) float xs[2][XELEMS];   // 2 x 10080 B
    __shared__ __align__(16) float ws[2][WELEMS];   // 2 x  2304 B

    const int tile = blockIdx.x;          // 0..7 : 2 across x 4 down
    const int b    = blockIdx.y;          // 0..127
    const int cg   = blockIdx.z;          // 0..3 cout group
    const int h0 = (tile >> 1) * TS_H;
    const int w0 = (tile & 1) * TS_W;
    const int tid = threadIdx.x;
    const int p  = tid & 15;              // pixel pair covers columns 2p, 2p+1
    const int py = tid >> 4;              // row 0..15

    // ---- precompute staging slots (fixed per thread for all chunks) ----
    int xrel[XSLOTS];
    unsigned vmask = 0;
#pragma unroll
    for (int s = 0; s < XSLOTS; s++) {
        int idx = tid + 256 * s;
        int ci  = idx / XCI;
        int rem = idx - ci * XCI;
        int r = rem / XROW, c = rem - r * XROW;
        int gh = h0 + r - 1, gw = w0 + c - 1;
        bool valid = (idx < XELEMS) && (c < 34) &&
                     ((unsigned)gh < (unsigned)H_) &&
                     ((unsigned)gw < (unsigned)W_);
        xrel[s] = ci * HW_ + gh * W_ + gw;
        if (valid) vmask |= (1u << s);
    }
    int wrel[3];
#pragma unroll
    for (int s = 0; s < 3; s++) {
        int idx = (tid + 256 * s) % WELEMS;
        int ci  = idx / (9 * COUT_PER);
        int rem = idx - ci * (9 * COUT_PER);
        int k  = rem >> 4;
        int co = rem & 15;
        wrel[s] = (cg * COUT_PER + co) * (C_ * 9) + ci * 9 + k;
    }
    const bool w2v = (tid < WELEMS - 512);

    const unsigned xs0 = (unsigned)__cvta_generic_to_shared(&xs[0][0]);
    const unsigned xs1 = (unsigned)__cvta_generic_to_shared(&xs[1][0]);
    const unsigned ws0 = (unsigned)__cvta_generic_to_shared(&ws[0][0]);
    const unsigned ws1 = (unsigned)__cvta_generic_to_shared(&ws[1][0]);
    const float* xbase = x + (size_t)b * CHW;

    // ---- zero both xs buffers once (halo slots are never rewritten) ----
    for (int i = tid; i < 2 * XELEMS; i += 256) (&xs[0][0])[i] = 0.0f;
    __syncthreads();

    // ---- prefetch chunk 0 ----
    {
#pragma unroll
        for (int s = 0; s < XSLOTS; s++)
            if (vmask & (1u << s))
                cpa4(xs0 + (unsigned)(tid + 256 * s) * 4u, xbase + xrel[s]);
        cpa4(ws0 + (unsigned)tid * 4u, w + wrel[0]);
        cpa4(ws0 + (unsigned)(tid + 256) * 4u, w + wrel[1]);
        if (w2v) cpa4(ws0 + (unsigned)(tid + 512) * 4u, w + wrel[2]);
        CP_COMMIT();
    }

    // Accumulators: lane pair = (co 2j, co 2j+1); tot0/a0 = pixel0, tot1/a1 = pixel1.
    u64 tot0[COUT_PER / 2], tot1[COUT_PER / 2];
#pragma unroll
    for (int j = 0; j < COUT_PER / 2; j++) { tot0[j] = 0ULL; tot1[j] = 0ULL; }

#pragma unroll 1
    for (int ch = 0; ch < NCHUNK; ch++) {
        const int bsel = ch & 1;
        if (ch + 1 < NCHUNK) {
            const float* xp = xbase + (ch + 1) * CIN_CHUNK * HW_;
            const float* wp = w + (ch + 1) * CIN_CHUNK * 9;
            const unsigned xb = bsel ? xs0 : xs1;
            const unsigned wb = bsel ? ws0 : ws1;
#pragma unroll
            for (int s = 0; s < XSLOTS; s++)
                if (vmask & (1u << s))
                    cpa4(xb + (unsigned)(tid + 256 * s) * 4u, xp + xrel[s]);
            cpa4(wb + (unsigned)tid * 4u, wp + wrel[0]);
            cpa4(wb + (unsigned)(tid + 256) * 4u, wp + wrel[1]);
            if (w2v) cpa4(wb + (unsigned)(tid + 512) * 4u, wp + wrel[2]);
            CP_COMMIT();
            CP_WAIT1();
        } else {
            CP_WAIT0();
        }
        __syncthreads();

        u64 a0[COUT_PER / 2], a1[COUT_PER / 2];
#pragma unroll
        for (int j = 0; j < COUT_PER / 2; j++) { a0[j] = 0ULL; a1[j] = 0ULL; }

#pragma unroll
        for (int ci = 0; ci < CIN_CHUNK; ci++) {
            const float* xb = &xs[bsel][ci * XCI + py * XROW + 2 * p];
#pragma unroll
            for (int kh = 0; kh < 3; kh++) {
                // splat the 4 needed input columns once per row
                u64 xd[4];
#pragma unroll
                for (int c = 0; c < 4; c++) xd[c] = dup2(xb[kh * XROW + c]);
#pragma unroll
                for (int kw = 0; kw < 3; kw++) {
                    const u64 x0 = xd[kw];
                    const u64 x1 = xd[kw + 1];
                    const ulonglong2* wq = (const ulonglong2*)
                        &ws[bsel][((ci * 3 + kh) * 3 + kw) * COUT_PER];
#pragma unroll
                    for (int q = 0; q < 4; q++) {     // 4 x LDS.128 broadcast
                        ulonglong2 wv = wq[q];
                        fma2(a0[q * 2 + 0], x0, wv.x);
                        fma2(a1[q * 2 + 0], x1, wv.x);
                        fma2(a0[q * 2 + 1], x0, wv.y);
                        fma2(a1[q * 2 + 1], x1, wv.y);
                    }
                }
            }
        }
        // fold 4-ci chunk into running totals (two-level summation, lane-wise)
#pragma unroll
        for (int j = 0; j < COUT_PER / 2; j++) {
            add2(tot0[j], a0[j]);
            add2(tot1[j], a1[j]);
        }
        __syncthreads();
    }

    const int h = h0 + py, wcol = w0 + 2 * p;
    float* zb = &g_z[(size_t)b * CHW + (size_t)cg * COUT_PER * HW_ + h * W_ + wcol];
#pragma unroll
    for (int j = 0; j < COUT_PER / 2; j++) {
        float e0, e1, f0, f1;
        unpk(tot0[j], e0, e1);    // pixel0: co=2j, co=2j+1
        unpk(tot1[j], f0, f1);    // pixel1
        *(float2*)&zb[(size_t)(2 * j) * HW_]     = make_float2(e0, f0);
        *(float2*)&zb[(size_t)(2 * j + 1) * HW_] = make_float2(e1, f1);
    }
}

// ---------------------------------------------------------------------------
// LIF scan over T, float4-vectorized: v += (x - v)/2 ; spike=(v>=1); reset 0.
// ---------------------------------------------------------------------------
__global__ __launch_bounds__(256)
void lif_kernel(float* __restrict__ out) {
    int i = blockIdx.x * blockDim.x + threadIdx.x;   // float4 index
    const float4* z4 = (const float4*)g_z;
    float4* o4 = (float4*)out;
    float4 v = make_float4(0.f, 0.f, 0.f, 0.f);
#pragma unroll
    for (int t = 0; t < T_; t++) {
        float4 xv = z4[(size_t)t * (INNER / 4) + i];
        v.x = v.x + (xv.x - v.x) * 0.5f;
        v.y = v.y + (xv.y - v.y) * 0.5f;
        v.z = v.z + (xv.z - v.z) * 0.5f;
        v.w = v.w + (xv.w - v.w) * 0.5f;
        float4 s;
        s.x = (v.x >= 1.0f) ? 1.0f : 0.0f;
        s.y = (v.y >= 1.0f) ? 1.0f : 0.0f;
        s.z = (v.z >= 1.0f) ? 1.0f : 0.0f;
        s.w = (v.w >= 1.0f) ? 1.0f : 0.0f;
        o4[(size_t)t * (INNER / 4) + i] = s;
        if (v.x >= 1.0f) v.x = 0.0f;
        if (v.y >= 1.0f) v.y = 0.0f;
        if (v.z >= 1.0f) v.z = 0.0f;
        if (v.w >= 1.0f) v.w = 0.0f;
    }
}

extern "C" void kernel_launch(void* const* d_in, const int* in_sizes, int n_in,
                              void* d_out, int out_size) {
    const float* x = (const float*)d_in[0];
    const float* w = (const float*)d_in[1];
    float* out = (float*)d_out;

    dim3 grid(8, B_, 4);    // 2x4 tiles, 128 images, 4 cout groups
    conv3x3_kernel<<<grid, 256>>>(x, w);
    lif_kernel<<<(INNER / 4) / 256, 256>>>(out);
}